// round 1
// baseline (speedup 1.0000x reference)
#include <cuda_runtime.h>

// NAM_42442866819214: Neural Additive Model
//   inputs [B,F] fp32; per-feature MLP 1 -> H1(relu) -> H2(relu) -> 1
//   outputs: out[0:B]   = sum_f contrib(b,f) + bias[0]
//            out[B:B+B*F] = contrib(b,f)   (dropout p=0 => identity)
//
// Key algebraic collapse (valid when b1 == 0 and b2 == 0, which the
// precompute kernel verifies at runtime):
//   relu(x*w) = x * (x>0 ? max(w,0) : min(w,0))
//   => layer-2 preact z_k = x * c_{s,k},  c_{s,k} = sum_i W2[i,k]*w1sel_i(s)
//   => contrib = x * d_s[f] + b3[f],
//      d_+[f] = sum_k W3[f,k]*max(c_{+,k},0)
//      d_-[f] = sum_k W3[f,k]*min(c_{-,k},0)
// Turns a 2144-MAC-per-element compute problem into a streaming op.

#define NB   8192
#define NF   128
#define NH1  64
#define NH2  32
#define ROWS 16   // batch rows per block in the main kernel

__device__ float g_dpos[NF];
__device__ float g_dneg[NF];
__device__ int   g_general;   // nonzero => b1/b2 not all zero -> general path

__global__ void nam_reset_flag() { g_general = 0; }

// One block per feature, 32 threads (one per H2 unit k).
__global__ void nam_precompute(const float* __restrict__ W1,
                               const float* __restrict__ b1,
                               const float* __restrict__ W2,
                               const float* __restrict__ b2,
                               const float* __restrict__ W3) {
    int f = blockIdx.x;
    int k = threadIdx.x;  // 0..31

    // Verify the collapse precondition: b1[f,:]==0 and b2[f,:]==0
    int nz = 0;
    if (b1[f * NH1 + k]      != 0.f) nz = 1;
    if (b1[f * NH1 + 32 + k] != 0.f) nz = 1;
    if (b2[f * NH2 + k]      != 0.f) nz = 1;
    if (__ballot_sync(0xffffffffu, nz)) {
        if (k == 0) atomicOr(&g_general, 1);
    }

    float cp = 0.f, cn = 0.f;
#pragma unroll
    for (int i = 0; i < NH1; i++) {
        float w  = W1[f * NH1 + i];
        float w2 = W2[(f * NH1 + i) * NH2 + k];
        cp = fmaf(w2, fmaxf(w, 0.f), cp);
        cn = fmaf(w2, fminf(w, 0.f), cn);
    }
    float w3 = W3[f * NH2 + k];
    float dp = w3 * fmaxf(cp, 0.f);   // x>0: relu(x*cp) = x*max(cp,0)
    float dn = w3 * fminf(cn, 0.f);   // x<0: relu(x*cn) = x*min(cn,0)

#pragma unroll
    for (int o = 16; o > 0; o >>= 1) {
        dp += __shfl_xor_sync(0xffffffffu, dp, o);
        dn += __shfl_xor_sync(0xffffffffu, dn, o);
    }
    if (k == 0) {
        g_dpos[f] = dp;
        g_dneg[f] = dn;
    }
}

// blockDim = NF (one thread per feature), each block handles ROWS batch rows.
__global__ void __launch_bounds__(NF)
nam_main(const float* __restrict__ inputs,
         const float* __restrict__ W1,
         const float* __restrict__ b1,
         const float* __restrict__ W2,
         const float* __restrict__ b2,
         const float* __restrict__ W3,
         const float* __restrict__ b3,
         const float* __restrict__ bias,
         float* __restrict__ out) {
    const int f  = threadIdx.x;
    const int b0 = blockIdx.x * ROWS;

    const bool fast = (g_general == 0);
    const float dp  = g_dpos[f];
    const float dn  = g_dneg[f];
    const float bf3 = b3[f];

    __shared__ float warpsum[ROWS * 4];
    float* contribs = out + NB;   // out[B : B+B*F]

#pragma unroll
    for (int r = 0; r < ROWS; r++) {
        const int b = b0 + r;
        const float x = inputs[b * NF + f];
        float c;
        if (fast) {
            c = fmaf(x, (x > 0.f ? dp : dn), bf3);
        } else {
            // General fallback: full per-element MLP (dead for this dataset,
            // keeps the kernel correct for arbitrary bias values).
            float acc = 0.f;
            for (int k = 0; k < NH2; k++) {
                float a = b2[f * NH2 + k];
                for (int i = 0; i < NH1; i++) {
                    float h1 = fmaxf(fmaf(x, W1[f * NH1 + i], b1[f * NH1 + i]), 0.f);
                    a = fmaf(h1, W2[(f * NH1 + i) * NH2 + k], a);
                }
                acc = fmaf(fmaxf(a, 0.f), W3[f * NH2 + k], acc);
            }
            c = acc + bf3;
        }
        contribs[b * NF + f] = c;

        // reduce c over the 128 features of this row
        float s = c;
#pragma unroll
        for (int o = 16; o > 0; o >>= 1)
            s += __shfl_xor_sync(0xffffffffu, s, o);
        if ((f & 31) == 0) warpsum[r * 4 + (f >> 5)] = s;
    }
    __syncthreads();
    if (f < ROWS) {
        float s = warpsum[f * 4 + 0] + warpsum[f * 4 + 1] +
                  warpsum[f * 4 + 2] + warpsum[f * 4 + 3];
        out[b0 + f] = s + bias[0];
    }
}

extern "C" void kernel_launch(void* const* d_in, const int* in_sizes, int n_in,
                              void* d_out, int out_size) {
    const float* inputs = (const float*)d_in[0];
    const float* W1     = (const float*)d_in[1];
    const float* b1     = (const float*)d_in[2];
    const float* W2     = (const float*)d_in[3];
    const float* b2     = (const float*)d_in[4];
    const float* W3     = (const float*)d_in[5];
    const float* b3     = (const float*)d_in[6];
    const float* bias   = (const float*)d_in[7];
    float* out = (float*)d_out;

    nam_reset_flag<<<1, 1>>>();
    nam_precompute<<<NF, 32>>>(W1, b1, W2, b2, W3);
    nam_main<<<NB / ROWS, NF>>>(inputs, W1, b1, W2, b2, W3, b3, bias, out);
}